// round 17
// baseline (speedup 1.0000x reference)
#include <cuda_runtime.h>
#include <cuda_fp16.h>
#include <cstdint>

// ---------------------------------------------------------------------------
// ChildSumTreeLSTM depth 17, D=H=128. R17: single-pass fp16 HMMA; registers
// cut (no B reg-prefetch) to reach 3 CTAs/SM on tlevel (24 warps of phase
// overlap); small-kernel band widened to nl<=1024; N=64 split levels 11-13.
// ---------------------------------------------------------------------------

#define DEPTH   17
#define HH      128
#define NNODES  ((1 << (DEPTH + 1)) - 1)
#define PITCH   136
#define BPITCH  72

__device__ float g_h[33554304L];
__device__ float g_c[33554304L];
// fp16 weight images, dense [k][n]. mats: 0..3 = W_i,W_f,W_o,W_u ; 4..7 = U_*
__device__ uint4 g_Wh[8][2048];

__device__ __forceinline__ float sigf(float v)  { return 1.0f / (1.0f + __expf(-v)); }
__device__ __forceinline__ float tanhx(float v) {
    float r; asm("tanh.approx.f32 %0, %1;" : "=f"(r) : "f"(v)); return r;
}
__device__ __forceinline__ uint32_t smem_u32(const void* p) {
    uint32_t a; asm("{ .reg .u64 t; cvta.to.shared.u64 t, %1; cvt.u32.u64 %0, t; }"
                    : "=r"(a) : "l"(p)); return a;
}
__device__ __forceinline__ void ldsm4(uint32_t& r0, uint32_t& r1, uint32_t& r2,
                                      uint32_t& r3, uint32_t a) {
    asm volatile("ldmatrix.sync.aligned.m8n8.x4.shared.b16 {%0,%1,%2,%3}, [%4];"
                 : "=r"(r0), "=r"(r1), "=r"(r2), "=r"(r3) : "r"(a));
}
__device__ __forceinline__ void ldsm4t(uint32_t& r0, uint32_t& r1, uint32_t& r2,
                                       uint32_t& r3, uint32_t a) {
    asm volatile("ldmatrix.sync.aligned.m8n8.x4.trans.shared.b16 {%0,%1,%2,%3}, [%4];"
                 : "=r"(r0), "=r"(r1), "=r"(r2), "=r"(r3) : "r"(a));
}
__device__ __forceinline__ void mmaH(float* c, uint32_t a0, uint32_t a1,
                                     uint32_t a2, uint32_t a3,
                                     uint32_t b0, uint32_t b1) {
    asm volatile("mma.sync.aligned.m16n8k16.row.col.f32.f16.f16.f32 "
                 "{%0,%1,%2,%3}, {%4,%5,%6,%7}, {%8,%9}, {%0,%1,%2,%3};"
                 : "+f"(c[0]), "+f"(c[1]), "+f"(c[2]), "+f"(c[3])
                 : "r"(a0), "r"(a1), "r"(a2), "r"(a3), "r"(b0), "r"(b1));
}

// single-pass fp16 GEMM: dacc[4][4] += A @ B. Warp: 16 rows x 32 cols.
__device__ __forceinline__ void gemm_H(float (*dacc)[4], uint32_t aH,
                                       uint32_t bB, int bstep)
{
#pragma unroll
    for (int kc = 0; kc < 8; ++kc) {
        uint32_t a0,a1,a2,a3;
        ldsm4(a0,a1,a2,a3, aH + kc*32);
        uint32_t bp = bB + kc*bstep;
        uint32_t b0,b1,b2,b3, b4,b5,b6,b7;
        ldsm4t(b0,b1,b2,b3, bp);
        ldsm4t(b4,b5,b6,b7, bp + 32);
        mmaH(dacc[0], a0,a1,a2,a3, b0,b1);
        mmaH(dacc[1], a0,a1,a2,a3, b2,b3);
        mmaH(dacc[2], a0,a1,a2,a3, b4,b5);
        mmaH(dacc[3], a0,a1,a2,a3, b6,b7);
    }
}

// direct B staging (no register prefetch): full tile, 256 threads
__device__ __forceinline__ void stage8(__half* Bp, int mat, int tid) {
    const uint4* src = g_Wh[mat];
#pragma unroll
    for (int q = 0; q < 8; ++q) {
        int i = tid + q*256, row = i >> 4, ch = i & 15;
        *(uint4*)(Bp + row*PITCH + ch*8) = src[i];
    }
}
// direct B staging: half tile (128 rows x 64 cols), 128 threads
__device__ __forceinline__ void stage4(__half* Bp, int mat, int c0u, int tid) {
    const uint4* src = g_Wh[mat];
#pragma unroll
    for (int q = 0; q < 8; ++q) {
        int i = tid + q*128, row = i >> 3, ch = i & 7;
        *(uint4*)(Bp + row*BPITCH + ch*8) = src[row*16 + c0u + ch];
    }
}

__global__ void conv_w_kernel(
    const float* __restrict__ W_i, const float* __restrict__ W_f,
    const float* __restrict__ W_o, const float* __restrict__ W_u,
    const float* __restrict__ U_i, const float* __restrict__ U_f,
    const float* __restrict__ U_o, const float* __restrict__ U_u)
{
    const float* mats[8] = { W_i, W_f, W_o, W_u, U_i, U_f, U_o, U_u };
    const float* M = mats[blockIdx.x];
    __half* dst = (__half*)&g_Wh[blockIdx.x][0];
    for (int idx = threadIdx.x; idx < 16384; idx += blockDim.x)
        dst[idx] = __float2half(M[idx]);
}

// convert one fp32 row-half (opt. pair sum) into fp16 smem
__device__ __forceinline__ void conv_row_h(__half* dh, int row, int half,
                                           const float* __restrict__ s0,
                                           const float* __restrict__ s1)
{
#pragma unroll
    for (int i = 0; i < 16; ++i) {
        float4 v = *(const float4*)(s0 + i*4);
        if (s1) {
            float4 w = *(const float4*)(s1 + i*4);
            v.x += w.x; v.y += w.y; v.z += w.z; v.w += w.w;
        }
        __half2 p0 = __floats2half2_rn(v.x, v.y);
        __half2 p1 = __floats2half2_rn(v.z, v.w);
        *(uint2*)(dh + row*PITCH + half + i*4) =
            make_uint2(*(uint32_t*)&p0, *(uint32_t*)&p1);
    }
}

#define ZERO4 { _Pragma("unroll") for (int t = 0; t < 4; ++t) \
        { dacc[t][0]=0.f; dacc[t][1]=0.f; dacc[t][2]=0.f; dacc[t][3]=0.f; } }

// ---------------------------------------------------------------------------
// Leaf: 32 leaves/block, 256 threads, up to 4 CTAs/SM. Gates u,i,o from x@W.
// ---------------------------------------------------------------------------
__global__ void __launch_bounds__(256, 3) leaf_kernel(
    const float* __restrict__ x,
    const float* __restrict__ b_i, const float* __restrict__ b_o,
    const float* __restrict__ b_u)
{
    extern __shared__ __align__(16) __half sm[];
    __half* Xh = sm;
    __half* Bp = sm + 32*PITCH;

    const int tid = threadIdx.x;
    const int w = tid >> 5, l = tid & 31;
    const int mg = w >> 2, nh = w & 3;
    const int lr = l & 15, lc = l >> 4;
    const int qr = l >> 2, qc2 = (l & 3) * 2;
    const long np = 131071L + (long)blockIdx.x * 32;

    if (tid < 64) {
        int row = tid >> 1, half = (tid & 1) * 64;
        conv_row_h(Xh, row, half, x + (np + row)*HH + half, nullptr);
    }
    stage8(Bp, 3, tid);                     // W_u
    __syncthreads();

    const uint32_t a_off = (uint32_t)((16*mg + lr)*PITCH + lc*8)*2;
    const uint32_t b_off = (uint32_t)(lr*PITCH + nh*32 + lc*8)*2;
    const uint32_t xH = smem_u32(Xh)+a_off;
    const uint32_t bB = smem_u32(Bp)+b_off;

    const long n0 = np + 16*mg + qr, n1 = n0 + 8;
    const int cbase = nh*32 + qc2;

    float dacc[4][4], cc[4][4];
#define SWAPB(M) do { __syncthreads(); stage8(Bp, M, tid); __syncthreads(); } while (0)

    ZERO4; gemm_H(dacc, xH, bB, 16*PITCH*2);           // x @ W_u
#pragma unroll
    for (int t = 0; t < 4; ++t) {
        float2 b = *(const float2*)(b_u + cbase + t*8);
        cc[t][0]=tanhx(dacc[t][0]+b.x); cc[t][1]=tanhx(dacc[t][1]+b.y);
        cc[t][2]=tanhx(dacc[t][2]+b.x); cc[t][3]=tanhx(dacc[t][3]+b.y);
    }
    SWAPB(0);                               // B = W_i
    ZERO4; gemm_H(dacc, xH, bB, 16*PITCH*2);
#pragma unroll
    for (int t = 0; t < 4; ++t) {
        float2 b = *(const float2*)(b_i + cbase + t*8);
        cc[t][0]*=sigf(dacc[t][0]+b.x); cc[t][1]*=sigf(dacc[t][1]+b.y);
        cc[t][2]*=sigf(dacc[t][2]+b.x); cc[t][3]*=sigf(dacc[t][3]+b.y);
    }
    SWAPB(2);                               // B = W_o
    ZERO4; gemm_H(dacc, xH, bB, 16*PITCH*2);
#pragma unroll
    for (int t = 0; t < 4; ++t) {
        int c = cbase + t*8;
        float2 b = *(const float2*)(b_o + c);
        float h0 = sigf(dacc[t][0]+b.x)*tanhx(cc[t][0]);
        float h1 = sigf(dacc[t][1]+b.y)*tanhx(cc[t][1]);
        float h2 = sigf(dacc[t][2]+b.x)*tanhx(cc[t][2]);
        float h3 = sigf(dacc[t][3]+b.y)*tanhx(cc[t][3]);
        *(float2*)(g_c + n0*HH + c) = make_float2(cc[t][0], cc[t][1]);
        *(float2*)(g_c + n1*HH + c) = make_float2(cc[t][2], cc[t][3]);
        *(float2*)(g_h + n0*HH + c) = make_float2(h0, h1);
        *(float2*)(g_h + n1*HH + c) = make_float2(h2, h3);
    }
#undef SWAPB
}

// ---------------------------------------------------------------------------
// Tensor level (full N=128): 32 parents/block, 256 threads, 3 CTAs/SM.
// A slots: X, SUM(h0+h1), S1(h1). smem 3*8704 + 34816 = 60928 B.
// ---------------------------------------------------------------------------
__global__ void __launch_bounds__(256, 3) tlevel_kernel(
    int sl, const float* __restrict__ x,
    const float* __restrict__ b_i, const float* __restrict__ b_f,
    const float* __restrict__ b_o, const float* __restrict__ b_u)
{
    constexpr int AS = 32 * PITCH;
    extern __shared__ __align__(16) __half sm[];
    __half* Xh  = sm;
    __half* SUh = sm + AS;
    __half* S1h = sm + 2*AS;
    __half* Bp  = sm + 3*AS;

    const int tid = threadIdx.x;
    const int w = tid >> 5, l = tid & 31;
    const int mg = w >> 2, nh = w & 3;
    const int lr = l & 15, lc = l >> 4;
    const int qr = l >> 2, qc2 = (l & 3) * 2;

    const long np = (long)sl + (long)blockIdx.x * 32;
    const long cb = 2*np + 1;

    if (tid < 192) {
        int slot = tid >> 6;                // 0=X, 1=SUM, 2=S1
        int row  = (tid & 63) >> 1;
        int half = (tid & 1) * 64;
        if (slot == 0)
            conv_row_h(Xh, row, half, x + (np + row)*HH + half, nullptr);
        else if (slot == 1)
            conv_row_h(SUh, row, half, g_h + (cb + 2*row)*HH + half,
                                       g_h + (cb + 2*row + 1)*HH + half);
        else
            conv_row_h(S1h, row, half, g_h + (cb + 2*row + 1)*HH + half, nullptr);
    }
    stage8(Bp, 3, tid);                     // W_u
    __syncthreads();

    const uint32_t a_off = (uint32_t)((16*mg + lr)*PITCH + lc*8)*2;
    const uint32_t b_off = (uint32_t)(lr*PITCH + nh*32 + lc*8)*2;
    const uint32_t xH  = smem_u32(Xh)+a_off;
    const uint32_t suH = smem_u32(SUh)+a_off;
    const uint32_t s1H = smem_u32(S1h)+a_off;
    const uint32_t bB  = smem_u32(Bp)+b_off;

    const long n0 = np + 16*mg + qr, n1 = n0 + 8;
    const int cbase = nh*32 + qc2;

    float dacc[4][4], cc[4][4], xf[4][4];
#define SWAPB(M) do { __syncthreads(); stage8(Bp, M, tid); __syncthreads(); } while (0)
#define BSTEP (16*PITCH*2)

    // ---- u ----
    ZERO4; gemm_H(dacc, xH, bB, BSTEP);     // x @ W_u
    SWAPB(7);                               // B = U_u
    gemm_H(dacc, suH, bB, BSTEP);
#pragma unroll
    for (int t = 0; t < 4; ++t) {
        float2 b = *(const float2*)(b_u + cbase + t*8);
        cc[t][0]=tanhx(dacc[t][0]+b.x); cc[t][1]=tanhx(dacc[t][1]+b.y);
        cc[t][2]=tanhx(dacc[t][2]+b.x); cc[t][3]=tanhx(dacc[t][3]+b.y);
    }
    // ---- i ----
    SWAPB(0);                               // B = W_i
    ZERO4; gemm_H(dacc, xH, bB, BSTEP);
    SWAPB(4);                               // B = U_i
    gemm_H(dacc, suH, bB, BSTEP);
#pragma unroll
    for (int t = 0; t < 4; ++t) {
        float2 b = *(const float2*)(b_i + cbase + t*8);
        cc[t][0]*=sigf(dacc[t][0]+b.x); cc[t][1]*=sigf(dacc[t][1]+b.y);
        cc[t][2]*=sigf(dacc[t][2]+b.x); cc[t][3]*=sigf(dacc[t][3]+b.y);
    }
    // ---- f ----
    SWAPB(1);                               // B = W_f
    ZERO4; gemm_H(dacc, xH, bB, BSTEP);
#pragma unroll
    for (int t = 0; t < 4; ++t) {
        float2 b = *(const float2*)(b_f + cbase + t*8);
        xf[t][0]=dacc[t][0]+b.x; xf[t][1]=dacc[t][1]+b.y;
        xf[t][2]=dacc[t][2]+b.x; xf[t][3]=dacc[t][3]+b.y;
    }
    SWAPB(5);                               // B = U_f
    ZERO4; gemm_H(dacc, s1H, bB, BSTEP);               // G1 = h1 @ U_f
#pragma unroll
    for (int t = 0; t < 4; ++t) {                      // f1 with child1 cell
        int c = cbase + t*8;
        float2 ca = *(const float2*)(g_c + (2*n0+2)*HH + c);
        float2 cbv = *(const float2*)(g_c + (2*n1+2)*HH + c);
        cc[t][0]+=sigf(dacc[t][0]+xf[t][0])*ca.x;
        cc[t][1]+=sigf(dacc[t][1]+xf[t][1])*ca.y;
        cc[t][2]+=sigf(dacc[t][2]+xf[t][2])*cbv.x;
        cc[t][3]+=sigf(dacc[t][3]+xf[t][3])*cbv.y;
        dacc[t][0]=-dacc[t][0]; dacc[t][1]=-dacc[t][1];
        dacc[t][2]=-dacc[t][2]; dacc[t][3]=-dacc[t][3];
    }
    gemm_H(dacc, suH, bB, BSTEP);                      // Gsum - G1 = h0 @ U_f
#pragma unroll
    for (int t = 0; t < 4; ++t) {                      // f0 with child0 cell
        int c = cbase + t*8;
        float2 ca = *(const float2*)(g_c + (2*n0+1)*HH + c);
        float2 cbv = *(const float2*)(g_c + (2*n1+1)*HH + c);
        cc[t][0]+=sigf(dacc[t][0]+xf[t][0])*ca.x;
        cc[t][1]+=sigf(dacc[t][1]+xf[t][1])*ca.y;
        cc[t][2]+=sigf(dacc[t][2]+xf[t][2])*cbv.x;
        cc[t][3]+=sigf(dacc[t][3]+xf[t][3])*cbv.y;
    }
    // ---- o + store ----
    SWAPB(2);                               // B = W_o
    ZERO4; gemm_H(dacc, xH, bB, BSTEP);
    SWAPB(6);                               // B = U_o
    gemm_H(dacc, suH, bB, BSTEP);
#pragma unroll
    for (int t = 0; t < 4; ++t) {
        int c = cbase + t*8;
        float2 b = *(const float2*)(b_o + c);
        float h0 = sigf(dacc[t][0]+b.x)*tanhx(cc[t][0]);
        float h1 = sigf(dacc[t][1]+b.y)*tanhx(cc[t][1]);
        float h2 = sigf(dacc[t][2]+b.x)*tanhx(cc[t][2]);
        float h3 = sigf(dacc[t][3]+b.y)*tanhx(cc[t][3]);
        *(float2*)(g_c + n0*HH + c) = make_float2(cc[t][0], cc[t][1]);
        *(float2*)(g_c + n1*HH + c) = make_float2(cc[t][2], cc[t][3]);
        *(float2*)(g_h + n0*HH + c) = make_float2(h0, h1);
        *(float2*)(g_h + n1*HH + c) = make_float2(h2, h3);
    }
#undef SWAPB
#undef BSTEP
}

// ---------------------------------------------------------------------------
// Column-split tensor level (N=64): 32 parents/block, 128 threads, 5 CTAs/SM.
// ---------------------------------------------------------------------------
__global__ void __launch_bounds__(128, 5) tlevel64_kernel(
    int sl, const float* __restrict__ x,
    const float* __restrict__ b_i, const float* __restrict__ b_f,
    const float* __restrict__ b_o, const float* __restrict__ b_u)
{
    constexpr int AS = 32 * PITCH;
    extern __shared__ __align__(16) __half sm[];
    __half* Xh  = sm;
    __half* SUh = sm + AS;
    __half* S1h = sm + 2*AS;
    __half* Bp  = sm + 3*AS;

    const int tid = threadIdx.x;
    const int w = tid >> 5, l = tid & 31;
    const int mg = w >> 1, nh = w & 1;
    const int lr = l & 15, lc = l >> 4;
    const int qr = l >> 2, qc2 = (l & 3) * 2;

    const int  c0  = (blockIdx.x & 1) * 64;
    const int  c0u = (blockIdx.x & 1) * 8;
    const long np  = (long)sl + (long)(blockIdx.x >> 1) * 32;
    const long cb  = 2*np + 1;

    for (int j = tid; j < 192; j += 128) {
        int slot = j >> 6;
        int row  = (j & 63) >> 1;
        int half = (j & 1) * 64;
        if (slot == 0)
            conv_row_h(Xh, row, half, x + (np + row)*HH + half, nullptr);
        else if (slot == 1)
            conv_row_h(SUh, row, half, g_h + (cb + 2*row)*HH + half,
                                       g_h + (cb + 2*row + 1)*HH + half);
        else
            conv_row_h(S1h, row, half, g_h + (cb + 2*row + 1)*HH + half, nullptr);
    }
    stage4(Bp, 3, c0u, tid);                // W_u half
    __syncthreads();

    const uint32_t a_off = (uint32_t)((16*mg + lr)*PITCH + lc*8)*2;
    const uint32_t b_off = (uint32_t)(lr*BPITCH + nh*32 + lc*8)*2;
    const uint32_t xH  = smem_u32(Xh)+a_off;
    const uint32_t suH = smem_u32(SUh)+a_off;
    const uint32_t s1H = smem_u32(S1h)+a_off;
    const uint32_t bB  = smem_u32(Bp)+b_off;

    const long n0 = np + 16*mg + qr, n1 = n0 + 8;
    const int cbase = c0 + nh*32 + qc2;

    float dacc[4][4], cc[4][4], xf[4][4];
#define SWAPB(M) do { __syncthreads(); stage4(Bp, M, c0u, tid); __syncthreads(); } while (0)
#define BSTEP (16*BPITCH*2)

    // ---- u ----
    ZERO4; gemm_H(dacc, xH, bB, BSTEP);
    SWAPB(7);
    gemm_H(dacc, suH, bB, BSTEP);
#pragma unroll
    for (int t = 0; t < 4; ++t) {
        float2 b = *(const float2*)(b_u + cbase + t*8);
        cc[t][0]=tanhx(dacc[t][0]+b.x); cc[t][1]=tanhx(dacc[t][1]+b.y);
        cc[t][2]=tanhx(dacc[t][2]+b.x); cc[t][3]=tanhx(dacc[t][3]+b.y);
    }
    // ---- i ----
    SWAPB(0);
    ZERO4; gemm_H(dacc, xH, bB, BSTEP);
    SWAPB(4);
    gemm_H(dacc, suH, bB, BSTEP);
#pragma unroll
    for (int t = 0; t < 4; ++t) {
        float2 b = *(const float2*)(b_i + cbase + t*8);
        cc[t][0]*=sigf(dacc[t][0]+b.x); cc[t][1]*=sigf(dacc[t][1]+b.y);
        cc[t][2]*=sigf(dacc[t][2]+b.x); cc[t][3]*=sigf(dacc[t][3]+b.y);
    }
    // ---- f ----
    SWAPB(1);
    ZERO4; gemm_H(dacc, xH, bB, BSTEP);
#pragma unroll
    for (int t = 0; t < 4; ++t) {
        float2 b = *(const float2*)(b_f + cbase + t*8);
        xf[t][0]=dacc[t][0]+b.x; xf[t][1]=dacc[t][1]+b.y;
        xf[t][2]=dacc[t][2]+b.x; xf[t][3]=dacc[t][3]+b.y;
    }
    SWAPB(5);
    ZERO4; gemm_H(dacc, s1H, bB, BSTEP);               // G1 = h1 @ U_f
#pragma unroll
    for (int t = 0; t < 4; ++t) {
        int c = cbase + t*8;
        float2 ca = *(const float2*)(g_c + (2*n0+2)*HH + c);
        float2 cbv = *(const float2*)(g_c + (2*n1+2)*HH + c);
        cc[t][0]+=sigf(dacc[t][0]+xf[t][0])*ca.x;
        cc[t][1]+=sigf(dacc[t][1]+xf[t][1])*ca.y;
        cc[t][2]+=sigf(dacc[t][2]+xf[t][2])*cbv.x;
        cc[t][3]+=sigf(dacc[t][3]+xf[t][3])*cbv.y;
        dacc[t][0]=-dacc[t][0]; dacc[t][1]=-dacc[t][1];
        dacc[t][2]=-dacc[t][2]; dacc[t][3]=-dacc[t][3];
    }
    gemm_H(dacc, suH, bB, BSTEP);                      // Gsum - G1 = h0 @ U_f
#pragma unroll
    for (int t = 0; t < 4; ++t) {
        int c = cbase + t*8;
        float2 ca = *(const float2*)(g_c + (2*n0+1)*HH + c);
        float2 cbv = *(const float2*)(g_c + (2*n1+1)*HH + c);
        cc[t][0]+=sigf(dacc[t][0]+xf[t][0])*ca.x;
        cc[t][1]+=sigf(dacc[t][1]+xf[t][1])*ca.y;
        cc[t][2]+=sigf(dacc[t][2]+xf[t][2])*cbv.x;
        cc[t][3]+=sigf(dacc[t][3]+xf[t][3])*cbv.y;
    }
    // ---- o + store ----
    SWAPB(2);
    ZERO4; gemm_H(dacc, xH, bB, BSTEP);
    SWAPB(6);
    gemm_H(dacc, suH, bB, BSTEP);
#pragma unroll
    for (int t = 0; t < 4; ++t) {
        int c = cbase + t*8;
        float2 b = *(const float2*)(b_o + c);
        float h0 = sigf(dacc[t][0]+b.x)*tanhx(cc[t][0]);
        float h1 = sigf(dacc[t][1]+b.y)*tanhx(cc[t][1]);
        float h2 = sigf(dacc[t][2]+b.x)*tanhx(cc[t][2]);
        float h3 = sigf(dacc[t][3]+b.y)*tanhx(cc[t][3]);
        *(float2*)(g_c + n0*HH + c) = make_float2(cc[t][0], cc[t][1]);
        *(float2*)(g_c + n1*HH + c) = make_float2(cc[t][2], cc[t][3]);
        *(float2*)(g_h + n0*HH + c) = make_float2(h0, h1);
        *(float2*)(g_h + n1*HH + c) = make_float2(h2, h3);
    }
#undef SWAPB
#undef BSTEP
}

// ---------------------------------------------------------------------------
// Small levels (nl <= 1024): one parent/block, 512 threads, 9 k-split matvecs.
// ---------------------------------------------------------------------------
__global__ void __launch_bounds__(512) small_level_kernel(
    int sl, const float* __restrict__ x,
    const float* __restrict__ W_i, const float* __restrict__ b_i, const float* __restrict__ U_i,
    const float* __restrict__ W_f, const float* __restrict__ b_f, const float* __restrict__ U_f,
    const float* __restrict__ W_o, const float* __restrict__ b_o, const float* __restrict__ U_o,
    const float* __restrict__ W_u, const float* __restrict__ b_u, const float* __restrict__ U_u)
{
    extern __shared__ float smf[];
    float* hs   = smf;              // [h~ | h0 | h1 | x] x 128
    float* part = smf + 512;        // [9][4][128]

    const int t = threadIdx.x;
    const long node = sl + blockIdx.x;
    const long ch0  = 2*node + 1;

    if (t < 128) {
        float h0 = g_h[ch0*HH + t];
        float h1 = g_h[(ch0+1)*HH + t];
        hs[128+t] = h0; hs[256+t] = h1; hs[t] = h0 + h1;
        hs[384+t] = x[node*HH + t];
    }
    __syncthreads();

    const int col = t & 127;
    const int q   = t >> 7;
    const int kb  = q * 32;

#define JOB(J, S, M) { float av = 0.f; const float* s = hs + (S)*128;          \
        _Pragma("unroll 8")                                                    \
        for (int k = 0; k < 32; ++k) av += s[kb+k] * (M)[(kb+k)*HH + col];     \
        part[((J)*4 + q)*128 + col] = av; }
    JOB(0, 0, U_i) JOB(1, 0, U_o) JOB(2, 0, U_u)
    JOB(3, 1, U_f) JOB(4, 2, U_f)
    JOB(5, 3, W_i) JOB(6, 3, W_f) JOB(7, 3, W_o) JOB(8, 3, W_u)
#undef JOB
    __syncthreads();

    if (t < 128) {
#define SUMP(J) (part[((J)*4+0)*128+t] + part[((J)*4+1)*128+t] + \
                 part[((J)*4+2)*128+t] + part[((J)*4+3)*128+t])
        float yi  = SUMP(0), yo = SUMP(1), yu = SUMP(2);
        float yf0 = SUMP(3), yf1 = SUMP(4);
        float xi  = SUMP(5) + b_i[t];
        float xfv = SUMP(6) + b_f[t];
        float xo  = SUMP(7) + b_o[t];
        float xu  = SUMP(8) + b_u[t];
#undef SUMP
        float c = sigf(xi+yi)*tanhx(xu+yu)
                + sigf(xfv+yf0)*g_c[ch0*HH+t] + sigf(xfv+yf1)*g_c[(ch0+1)*HH+t];
        g_c[node*HH+t] = c;
        g_h[node*HH+t] = sigf(xo+yo)*tanhx(c);
    }
}

__global__ void out_kernel(float* __restrict__ out)
{
    int t = threadIdx.x;
    out[t] = (t < 128) ? g_h[t] : g_c[t - 128];
}

// ---------------------------------------------------------------------------
extern "C" void kernel_launch(void* const* d_in, const int* in_sizes, int n_in,
                              void* d_out, int out_size)
{
    const float* x   = (const float*)d_in[0];
    const float* W_i = (const float*)d_in[1];
    const float* b_i = (const float*)d_in[2];
    const float* U_i = (const float*)d_in[3];
    const float* W_f = (const float*)d_in[4];
    const float* b_f = (const float*)d_in[5];
    const float* U_f = (const float*)d_in[6];
    const float* W_o = (const float*)d_in[7];
    const float* b_o = (const float*)d_in[8];
    const float* U_o = (const float*)d_in[9];
    const float* W_u = (const float*)d_in[10];
    const float* b_u = (const float*)d_in[11];
    const float* U_u = (const float*)d_in[12];

    const int SMEM_T   = (3*32*PITCH + 128*PITCH) * 2;   // 60928
    const int SMEM_T64 = 3*32*PITCH*2 + 128*BPITCH*2;    // 44544
    const int SMEM_L   = (32*PITCH + 128*PITCH) * 2;     // 43520
    const int SMEM_S   = (512 + 9*4*128) * 4;
    cudaFuncSetAttribute(tlevel_kernel,   cudaFuncAttributeMaxDynamicSharedMemorySize, SMEM_T);
    cudaFuncSetAttribute(tlevel64_kernel, cudaFuncAttributeMaxDynamicSharedMemorySize, SMEM_T64);
    cudaFuncSetAttribute(leaf_kernel,     cudaFuncAttributeMaxDynamicSharedMemorySize, SMEM_L);
    cudaFuncSetAttribute(small_level_kernel, cudaFuncAttributeMaxDynamicSharedMemorySize, SMEM_S);

    conv_w_kernel<<<8, 256>>>(W_i, W_f, W_o, W_u, U_i, U_f, U_o, U_u);

    leaf_kernel<<<131072 / 32, 256, SMEM_L>>>(x, b_i, b_o, b_u);

    for (int l = DEPTH - 1; l >= 0; --l) {
        int nl = 1 << l;
        int sl = nl - 1;
        if (nl >= 16384)
            tlevel_kernel<<<nl / 32, 256, SMEM_T>>>(sl, x, b_i, b_f, b_o, b_u);
        else if (nl >= 2048)
            tlevel64_kernel<<<(nl / 32) * 2, 128, SMEM_T64>>>(sl, x, b_i, b_f, b_o, b_u);
        else
            small_level_kernel<<<nl, 512, SMEM_S>>>(sl, x,
                W_i, b_i, U_i, W_f, b_f, U_f, W_o, b_o, U_o, W_u, b_u, U_u);
    }

    out_kernel<<<1, 256>>>((float*)d_out);
}